// round 3
// baseline (speedup 1.0000x reference)
#include <cuda_runtime.h>
#include <cuda_fp16.h>
#include <cstdint>

// Problem constants
#define BATCH    8
#define NHEADS   8
#define DHEAD    64
#define SEQ      1024
#define BM       128     // q rows per CTA (8 warps x 16)
#define BN       64      // k cols per inner tile
#define NTHREADS 256
#define NKT      (SEQ / BN)   // 16
#define LDQ      136     // halves per smem row of sQ ([dd][t], t=128 + pad 8)
#define LDK      72      // halves per smem row of sV ([dd][t], t=64 + pad 8)
#define LDKI     144     // halves per dd-PAIR row of sKi (64 t * 2 interleaved + pad) = 72 words

__device__ __forceinline__ uint32_t packh(__half lo, __half hi) {
    return ((uint32_t)__half_as_ushort(hi) << 16) | (uint32_t)__half_as_ushort(lo);
}
__device__ __forceinline__ uint32_t f2h2(float x, float y) {
    __half2 h = __floats2half2_rn(x, y);
    return *reinterpret_cast<uint32_t*>(&h);
}
__device__ __forceinline__ void mma16816(float* d, const uint32_t* a, uint32_t b0, uint32_t b1) {
    asm volatile(
        "mma.sync.aligned.m16n8k16.row.col.f32.f16.f16.f32 "
        "{%0,%1,%2,%3}, {%4,%5,%6,%7}, {%8,%9}, {%0,%1,%2,%3};\n"
        : "+f"(d[0]), "+f"(d[1]), "+f"(d[2]), "+f"(d[3])
        : "r"(a[0]), "r"(a[1]), "r"(a[2]), "r"(a[3]), "r"(b0), "r"(b1));
}

__global__ __launch_bounds__(NTHREADS, 1)
void mha_flash_kernel(const float* __restrict__ q, const float* __restrict__ k,
                      const float* __restrict__ v, const float* __restrict__ mask,
                      float* __restrict__ out) {
    __shared__ __align__(16) __half sQ[DHEAD * LDQ];
    __shared__ __align__(16) __half sKi[(DHEAD / 2) * LDKI];   // dd-pair interleaved
    __shared__ __align__(16) __half sV[DHEAD * LDK];

    const int qt    = blockIdx.x;   // 0..7 : q tile
    const int bh    = blockIdx.y;   // 0..63
    const int batch = bh >> 3;
    const float* qb = q + (size_t)bh * (DHEAD * SEQ);
    const float* kb = k + (size_t)bh * (DHEAD * SEQ);
    const float* vb = v + (size_t)bh * (DHEAD * SEQ);
    const float* mb = mask + (size_t)batch * SEQ * SEQ;
    float*       ob = out + (size_t)bh * (DHEAD * SEQ);

    const int tid  = threadIdx.x;
    const int warp = tid >> 5;
    const int lane = tid & 31;
    const int g    = lane >> 2;   // 0..7
    const int c4   = lane & 3;    // 0..3

    const int t0 = qt * BM;

    // ---- Load Q tile: gmem [dd][t] fp32 -> smem [dd][t] fp16, fold 0.125 scale (exact) ----
    #pragma unroll
    for (int i = tid; i < DHEAD * (BM / 2); i += NTHREADS) {
        int dd = i >> 6;          // BM/2 = 64 float2 per row
        int t2 = i & 63;
        float2 val = *reinterpret_cast<const float2*>(qb + (size_t)dd * SEQ + t0 + 2 * t2);
        *reinterpret_cast<__half2*>(&sQ[dd * LDQ + 2 * t2]) =
            __floats2half2_rn(val.x * 0.125f, val.y * 0.125f);
    }

    // ---- Prefetch K/V tile 0 into registers ----
    // K: each thread handles (dd pair dp, t pair 2*t2): two coalesced LDG.64 from rows 2dp, 2dp+1
    float2 rka[4], rkb[4], rv[8];
    {
        #pragma unroll
        for (int u = 0; u < 4; u++) {
            int i = tid + u * NTHREADS;   // 0..1023
            int dp = i >> 5;              // 0..31
            int t2 = i & 31;
            const float* src = kb + (size_t)(2 * dp) * SEQ + 2 * t2;
            rka[u] = *reinterpret_cast<const float2*>(src);
            rkb[u] = *reinterpret_cast<const float2*>(src + SEQ);
        }
        #pragma unroll
        for (int u = 0; u < 8; u++) {
            int i = tid + u * NTHREADS;
            int dd = i >> 5;
            int t2 = i & 31;
            rv[u] = *reinterpret_cast<const float2*>(vb + (size_t)dd * SEQ + 2 * t2);
        }
    }

    __syncthreads();

    // ---- Q A-fragments (row-major A of m16n8k16), kept in registers for whole loop ----
    const int r0 = warp * 16 + g;   // within tile
    const int r8 = r0 + 8;
    uint32_t aq[4][4];
    #pragma unroll
    for (int kk = 0; kk < 4; kk++) {
        int col = 16 * kk + 2 * c4;
        aq[kk][0] = packh(sQ[(col    ) * LDQ + r0], sQ[(col + 1) * LDQ + r0]);
        aq[kk][1] = packh(sQ[(col    ) * LDQ + r8], sQ[(col + 1) * LDQ + r8]);
        aq[kk][2] = packh(sQ[(col + 8) * LDQ + r0], sQ[(col + 9) * LDQ + r0]);
        aq[kk][3] = packh(sQ[(col + 8) * LDQ + r8], sQ[(col + 9) * LDQ + r8]);
    }

    // ---- Flash state ----
    float m0 = -1e30f, m8 = -1e30f, l0 = 0.f, l8 = 0.f;
    float o[8][4];
    #pragma unroll
    for (int j = 0; j < 8; j++) { o[j][0] = 0.f; o[j][1] = 0.f; o[j][2] = 0.f; o[j][3] = 0.f; }

    const int qr0 = t0 + r0;
    const int qr8 = t0 + r8;

    for (int kt = 0; kt < NKT; kt++) {
        const int kbase = kt * BN;

        // ---- Publish prefetched K/V tile to smem (fp32 -> fp16) ----
        // K interleaved: element (dd, t) -> sKi[(dd>>1)*LDKI + 2t + (dd&1)]
        #pragma unroll
        for (int u = 0; u < 4; u++) {
            int i = tid + u * NTHREADS;
            int dp = i >> 5;
            int t2 = i & 31;
            *reinterpret_cast<uint32_t*>(&sKi[dp * LDKI + 4 * t2    ]) = f2h2(rka[u].x, rkb[u].x);
            *reinterpret_cast<uint32_t*>(&sKi[dp * LDKI + 4 * t2 + 2]) = f2h2(rka[u].y, rkb[u].y);
        }
        #pragma unroll
        for (int u = 0; u < 8; u++) {
            int i = tid + u * NTHREADS;
            int dd = i >> 5;
            int t2 = i & 31;
            *reinterpret_cast<__half2*>(&sV[dd * LDK + 2 * t2]) = __floats2half2_rn(rv[u].x, rv[u].y);
        }
        __syncthreads();

        // ---- Prefetch next tile while we compute on this one ----
        if (kt + 1 < NKT) {
            const int nbase = kbase + BN;
            #pragma unroll
            for (int u = 0; u < 4; u++) {
                int i = tid + u * NTHREADS;
                int dp = i >> 5;
                int t2 = i & 31;
                const float* src = kb + (size_t)(2 * dp) * SEQ + nbase + 2 * t2;
                rka[u] = *reinterpret_cast<const float2*>(src);
                rkb[u] = *reinterpret_cast<const float2*>(src + SEQ);
            }
            #pragma unroll
            for (int u = 0; u < 8; u++) {
                int i = tid + u * NTHREADS;
                int dd = i >> 5;
                int t2 = i & 31;
                rv[u] = *reinterpret_cast<const float2*>(vb + (size_t)dd * SEQ + nbase + 2 * t2);
            }
        }

        // ---- Scores: S = (Q*0.125) @ K^T  (fp32 accum) ----
        float s[8][4];
        #pragma unroll
        for (int j = 0; j < 8; j++) { s[j][0] = 0.f; s[j][1] = 0.f; s[j][2] = 0.f; s[j][3] = 0.f; }

        #pragma unroll
        for (int kk = 0; kk < 4; kk++) {
            // B frag: pair-row = 8kk + c4 (covers dd rows 16kk+2c4, +1); b1 at pair-row +4
            const __half* kp = &sKi[(8 * kk + c4) * LDKI];
            #pragma unroll
            for (int j = 0; j < 8; j++) {
                int tk = 8 * j + g;
                uint32_t b0 = *reinterpret_cast<const uint32_t*>(kp + 2 * tk);
                uint32_t b1 = *reinterpret_cast<const uint32_t*>(kp + 4 * LDKI + 2 * tk);
                mma16816(s[j], aq[kk], b0, b1);
            }
        }

        // ---- Mask (additive {0,-10000} -> drop where != 0) ----
        const float* mrow0 = mb + (size_t)qr0 * SEQ + kbase;
        const float* mrow8 = mb + (size_t)qr8 * SEQ + kbase;
        #pragma unroll
        for (int j = 0; j < 8; j++) {
            int cc = 8 * j + 2 * c4;
            float2 mk0 = *reinterpret_cast<const float2*>(mrow0 + cc);
            float2 mk8 = *reinterpret_cast<const float2*>(mrow8 + cc);
            if (mk0.x != 0.f) s[j][0] = -1e30f;
            if (mk0.y != 0.f) s[j][1] = -1e30f;
            if (mk8.x != 0.f) s[j][2] = -1e30f;
            if (mk8.y != 0.f) s[j][3] = -1e30f;
        }

        // ---- Online softmax (rows r0 and r8) ----
        float vmax0 = -1e30f, vmax8 = -1e30f;
        #pragma unroll
        for (int j = 0; j < 8; j++) {
            vmax0 = fmaxf(vmax0, fmaxf(s[j][0], s[j][1]));
            vmax8 = fmaxf(vmax8, fmaxf(s[j][2], s[j][3]));
        }
        vmax0 = fmaxf(vmax0, __shfl_xor_sync(0xffffffffu, vmax0, 1));
        vmax0 = fmaxf(vmax0, __shfl_xor_sync(0xffffffffu, vmax0, 2));
        vmax8 = fmaxf(vmax8, __shfl_xor_sync(0xffffffffu, vmax8, 1));
        vmax8 = fmaxf(vmax8, __shfl_xor_sync(0xffffffffu, vmax8, 2));

        float mn0 = fmaxf(m0, vmax0);
        float mn8 = fmaxf(m8, vmax8);
        float alpha0 = __expf(m0 - mn0);
        float alpha8 = __expf(m8 - mn8);
        m0 = mn0; m8 = mn8;

        float sum0 = 0.f, sum8 = 0.f;
        #pragma unroll
        for (int j = 0; j < 8; j++) {
            float p0 = (s[j][0] > -1e29f) ? __expf(s[j][0] - mn0) : 0.f;
            float p1 = (s[j][1] > -1e29f) ? __expf(s[j][1] - mn0) : 0.f;
            float p2 = (s[j][2] > -1e29f) ? __expf(s[j][2] - mn8) : 0.f;
            float p3 = (s[j][3] > -1e29f) ? __expf(s[j][3] - mn8) : 0.f;
            sum0 += p0 + p1;
            sum8 += p2 + p3;
            s[j][0] = p0; s[j][1] = p1; s[j][2] = p2; s[j][3] = p3;
        }
        sum0 += __shfl_xor_sync(0xffffffffu, sum0, 1);
        sum0 += __shfl_xor_sync(0xffffffffu, sum0, 2);
        sum8 += __shfl_xor_sync(0xffffffffu, sum8, 1);
        sum8 += __shfl_xor_sync(0xffffffffu, sum8, 2);

        l0 = l0 * alpha0 + sum0;
        l8 = l8 * alpha8 + sum8;
        #pragma unroll
        for (int j = 0; j < 8; j++) {
            o[j][0] *= alpha0; o[j][1] *= alpha0;
            o[j][2] *= alpha8; o[j][3] *= alpha8;
        }

        // ---- P fragments: accumulator layout == A-fragment layout (flash trick) ----
        uint32_t ap[4][4];
        #pragma unroll
        for (int kk = 0; kk < 4; kk++) {
            int j0 = 2 * kk, j1 = 2 * kk + 1;
            ap[kk][0] = f2h2(s[j0][0], s[j0][1]);
            ap[kk][1] = f2h2(s[j0][2], s[j0][3]);
            ap[kk][2] = f2h2(s[j1][0], s[j1][1]);
            ap[kk][3] = f2h2(s[j1][2], s[j1][3]);
        }

        // ---- O += P @ V : V B-fragments are single LDS.32 from sV[dd][t] ----
        #pragma unroll
        for (int kk = 0; kk < 4; kk++) {
            int trow = 16 * kk + 2 * c4;
            #pragma unroll
            for (int j = 0; j < 8; j++) {
                int dd = 8 * j + g;
                uint32_t b0 = *reinterpret_cast<const uint32_t*>(&sV[dd * LDK + trow]);
                uint32_t b1 = *reinterpret_cast<const uint32_t*>(&sV[dd * LDK + trow + 8]);
                mma16816(o[j], ap[kk], b0, b1);
            }
        }
        __syncthreads();
    }

    // ---- Epilogue: out[b][head*64+dd][t] = o / l ----
    float il0 = 1.f / l0;
    float il8 = 1.f / l8;
    #pragma unroll
    for (int j = 0; j < 8; j++) {
        int dd = 8 * j + 2 * c4;
        ob[(size_t)(dd    ) * SEQ + qr0] = o[j][0] * il0;
        ob[(size_t)(dd + 1) * SEQ + qr0] = o[j][1] * il0;
        ob[(size_t)(dd    ) * SEQ + qr8] = o[j][2] * il8;
        ob[(size_t)(dd + 1) * SEQ + qr8] = o[j][3] * il8;
    }
}

extern "C" void kernel_launch(void* const* d_in, const int* in_sizes, int n_in,
                              void* d_out, int out_size) {
    const float* q    = (const float*)d_in[0];
    const float* k    = (const float*)d_in[1];
    const float* v    = (const float*)d_in[2];
    const float* mask = (const float*)d_in[3];
    float* out = (float*)d_out;

    dim3 grid(SEQ / BM, BATCH * NHEADS);   // (8, 64)
    dim3 block(NTHREADS);
    mha_flash_kernel<<<grid, block>>>(q, k, v, mask, out);
}

// round 4
// speedup vs baseline: 1.0234x; 1.0234x over previous
#include <cuda_runtime.h>
#include <cuda_fp16.h>
#include <cstdint>

// Problem constants
#define BATCH    8
#define NHEADS   8
#define DHEAD    64
#define SEQ      1024
#define BM       64      // q rows per CTA (4 warps x 16)
#define BN       64      // k cols per inner tile
#define NTHREADS 128
#define NWARPS   4
#define NKT      (SEQ / BN)   // 16
#define LDQ      72      // halves per smem row of sQ ([dd][t], t=64 + pad 8)
#define LDK      72      // halves per smem row of sV ([dd][t], t=64 + pad 8)
#define LDKI     144     // halves per dd-PAIR row of sKi (64 t * 2 interleaved + pad)

__device__ __forceinline__ uint32_t packh(__half lo, __half hi) {
    return ((uint32_t)__half_as_ushort(hi) << 16) | (uint32_t)__half_as_ushort(lo);
}
__device__ __forceinline__ uint32_t f2h2(float x, float y) {
    __half2 h = __floats2half2_rn(x, y);
    return *reinterpret_cast<uint32_t*>(&h);
}
__device__ __forceinline__ void mma16816(float* d, const uint32_t* a, uint32_t b0, uint32_t b1) {
    asm volatile(
        "mma.sync.aligned.m16n8k16.row.col.f32.f16.f16.f32 "
        "{%0,%1,%2,%3}, {%4,%5,%6,%7}, {%8,%9}, {%0,%1,%2,%3};\n"
        : "+f"(d[0]), "+f"(d[1]), "+f"(d[2]), "+f"(d[3])
        : "r"(a[0]), "r"(a[1]), "r"(a[2]), "r"(a[3]), "r"(b0), "r"(b1));
}

__global__ __launch_bounds__(NTHREADS, 2)
void mha_flash_kernel(const float* __restrict__ q, const float* __restrict__ k,
                      const float* __restrict__ v, const float* __restrict__ mask,
                      float* __restrict__ out) {
    __shared__ __align__(16) __half sQ[DHEAD * LDQ];
    __shared__ __align__(16) __half sKi[(DHEAD / 2) * LDKI];   // dd-pair interleaved
    __shared__ __align__(16) __half sV[DHEAD * LDK];

    const int qt    = blockIdx.x;   // 0..15 : q tile
    const int bh    = blockIdx.y;   // 0..63
    const int batch = bh >> 3;
    const float* qb = q + (size_t)bh * (DHEAD * SEQ);
    const float* kb = k + (size_t)bh * (DHEAD * SEQ);
    const float* vb = v + (size_t)bh * (DHEAD * SEQ);
    const float* mb = mask + (size_t)batch * SEQ * SEQ;
    float*       ob = out + (size_t)bh * (DHEAD * SEQ);

    const int tid  = threadIdx.x;
    const int warp = tid >> 5;
    const int lane = tid & 31;
    const int g    = lane >> 2;   // 0..7
    const int c4   = lane & 3;    // 0..3

    const int t0 = qt * BM;

    // ---- Load Q tile: gmem [dd][t] fp32 -> smem [dd][t] fp16, fold 0.125 scale (exact) ----
    #pragma unroll
    for (int i = tid; i < DHEAD * (BM / 2); i += NTHREADS) {
        int dd = i >> 5;          // BM/2 = 32 float2 per row
        int t2 = i & 31;
        float2 val = *reinterpret_cast<const float2*>(qb + (size_t)dd * SEQ + t0 + 2 * t2);
        *reinterpret_cast<__half2*>(&sQ[dd * LDQ + 2 * t2]) =
            __floats2half2_rn(val.x * 0.125f, val.y * 0.125f);
    }

    // ---- Prefetch K/V tile 0 into registers ----
    float2 rka[8], rkb[8], rv[16];
    {
        #pragma unroll
        for (int u = 0; u < 8; u++) {
            int i = tid + u * NTHREADS;   // 0..1023
            int dp = i >> 5;              // 0..31
            int t2 = i & 31;
            const float* src = kb + (size_t)(2 * dp) * SEQ + 2 * t2;
            rka[u] = *reinterpret_cast<const float2*>(src);
            rkb[u] = *reinterpret_cast<const float2*>(src + SEQ);
        }
        #pragma unroll
        for (int u = 0; u < 16; u++) {
            int i = tid + u * NTHREADS;   // 0..2047
            int dd = i >> 5;              // 0..63
            int t2 = i & 31;
            rv[u] = *reinterpret_cast<const float2*>(vb + (size_t)dd * SEQ + 2 * t2);
        }
    }

    __syncthreads();

    // ---- Q A-fragments (row-major A of m16n8k16), kept in registers for whole loop ----
    const int r0 = warp * 16 + g;   // within tile
    const int r8 = r0 + 8;
    uint32_t aq[4][4];
    #pragma unroll
    for (int kk = 0; kk < 4; kk++) {
        int col = 16 * kk + 2 * c4;
        aq[kk][0] = packh(sQ[(col    ) * LDQ + r0], sQ[(col + 1) * LDQ + r0]);
        aq[kk][1] = packh(sQ[(col    ) * LDQ + r8], sQ[(col + 1) * LDQ + r8]);
        aq[kk][2] = packh(sQ[(col + 8) * LDQ + r0], sQ[(col + 9) * LDQ + r0]);
        aq[kk][3] = packh(sQ[(col + 8) * LDQ + r8], sQ[(col + 9) * LDQ + r8]);
    }

    // ---- Flash state ----
    float m0 = -1e30f, m8 = -1e30f, l0 = 0.f, l8 = 0.f;
    float o[8][4];
    #pragma unroll
    for (int j = 0; j < 8; j++) { o[j][0] = 0.f; o[j][1] = 0.f; o[j][2] = 0.f; o[j][3] = 0.f; }

    const int qr0 = t0 + r0;
    const int qr8 = t0 + r8;

    for (int kt = 0; kt < NKT; kt++) {
        const int kbase = kt * BN;

        // ---- Publish prefetched K/V tile to smem (fp32 -> fp16) ----
        // K interleaved: element (dd, t) -> sKi[(dd>>1)*LDKI + 2t + (dd&1)]
        #pragma unroll
        for (int u = 0; u < 8; u++) {
            int i = tid + u * NTHREADS;
            int dp = i >> 5;
            int t2 = i & 31;
            *reinterpret_cast<uint32_t*>(&sKi[dp * LDKI + 4 * t2    ]) = f2h2(rka[u].x, rkb[u].x);
            *reinterpret_cast<uint32_t*>(&sKi[dp * LDKI + 4 * t2 + 2]) = f2h2(rka[u].y, rkb[u].y);
        }
        #pragma unroll
        for (int u = 0; u < 16; u++) {
            int i = tid + u * NTHREADS;
            int dd = i >> 5;
            int t2 = i & 31;
            *reinterpret_cast<__half2*>(&sV[dd * LDK + 2 * t2]) = __floats2half2_rn(rv[u].x, rv[u].y);
        }
        __syncthreads();

        // ---- Mask loads FIRST (hoisted): independent of smem, cover L2 latency with QK MMAs ----
        const float* mrow0 = mb + (size_t)qr0 * SEQ + kbase;
        const float* mrow8 = mb + (size_t)qr8 * SEQ + kbase;
        float2 mk0[8], mk8[8];
        #pragma unroll
        for (int j = 0; j < 8; j++) {
            int cc = 8 * j + 2 * c4;
            mk0[j] = *reinterpret_cast<const float2*>(mrow0 + cc);
            mk8[j] = *reinterpret_cast<const float2*>(mrow8 + cc);
        }

        // ---- Prefetch next K/V tile while we compute on this one ----
        if (kt + 1 < NKT) {
            const int nbase = kbase + BN;
            #pragma unroll
            for (int u = 0; u < 8; u++) {
                int i = tid + u * NTHREADS;
                int dp = i >> 5;
                int t2 = i & 31;
                const float* src = kb + (size_t)(2 * dp) * SEQ + nbase + 2 * t2;
                rka[u] = *reinterpret_cast<const float2*>(src);
                rkb[u] = *reinterpret_cast<const float2*>(src + SEQ);
            }
            #pragma unroll
            for (int u = 0; u < 16; u++) {
                int i = tid + u * NTHREADS;
                int dd = i >> 5;
                int t2 = i & 31;
                rv[u] = *reinterpret_cast<const float2*>(vb + (size_t)dd * SEQ + nbase + 2 * t2);
            }
        }

        // ---- Scores: S = (Q*0.125) @ K^T  (fp32 accum) ----
        float s[8][4];
        #pragma unroll
        for (int j = 0; j < 8; j++) { s[j][0] = 0.f; s[j][1] = 0.f; s[j][2] = 0.f; s[j][3] = 0.f; }

        #pragma unroll
        for (int kk = 0; kk < 4; kk++) {
            const __half* kp = &sKi[(8 * kk + c4) * LDKI];
            #pragma unroll
            for (int j = 0; j < 8; j++) {
                int tk = 8 * j + g;
                uint32_t b0 = *reinterpret_cast<const uint32_t*>(kp + 2 * tk);
                uint32_t b1 = *reinterpret_cast<const uint32_t*>(kp + 4 * LDKI + 2 * tk);
                mma16816(s[j], aq[kk], b0, b1);
            }
        }

        // ---- Apply mask (additive {0,-10000} -> drop where != 0) ----
        #pragma unroll
        for (int j = 0; j < 8; j++) {
            if (mk0[j].x != 0.f) s[j][0] = -1e30f;
            if (mk0[j].y != 0.f) s[j][1] = -1e30f;
            if (mk8[j].x != 0.f) s[j][2] = -1e30f;
            if (mk8[j].y != 0.f) s[j][3] = -1e30f;
        }

        // ---- Online softmax (rows r0 and r8) ----
        float vmax0 = -1e30f, vmax8 = -1e30f;
        #pragma unroll
        for (int j = 0; j < 8; j++) {
            vmax0 = fmaxf(vmax0, fmaxf(s[j][0], s[j][1]));
            vmax8 = fmaxf(vmax8, fmaxf(s[j][2], s[j][3]));
        }
        vmax0 = fmaxf(vmax0, __shfl_xor_sync(0xffffffffu, vmax0, 1));
        vmax0 = fmaxf(vmax0, __shfl_xor_sync(0xffffffffu, vmax0, 2));
        vmax8 = fmaxf(vmax8, __shfl_xor_sync(0xffffffffu, vmax8, 1));
        vmax8 = fmaxf(vmax8, __shfl_xor_sync(0xffffffffu, vmax8, 2));

        float mn0 = fmaxf(m0, vmax0);
        float mn8 = fmaxf(m8, vmax8);
        float alpha0 = __expf(m0 - mn0);
        float alpha8 = __expf(m8 - mn8);
        m0 = mn0; m8 = mn8;

        float sum0 = 0.f, sum8 = 0.f;
        #pragma unroll
        for (int j = 0; j < 8; j++) {
            float p0 = (s[j][0] > -1e29f) ? __expf(s[j][0] - mn0) : 0.f;
            float p1 = (s[j][1] > -1e29f) ? __expf(s[j][1] - mn0) : 0.f;
            float p2 = (s[j][2] > -1e29f) ? __expf(s[j][2] - mn8) : 0.f;
            float p3 = (s[j][3] > -1e29f) ? __expf(s[j][3] - mn8) : 0.f;
            sum0 += p0 + p1;
            sum8 += p2 + p3;
            s[j][0] = p0; s[j][1] = p1; s[j][2] = p2; s[j][3] = p3;
        }
        sum0 += __shfl_xor_sync(0xffffffffu, sum0, 1);
        sum0 += __shfl_xor_sync(0xffffffffu, sum0, 2);
        sum8 += __shfl_xor_sync(0xffffffffu, sum8, 1);
        sum8 += __shfl_xor_sync(0xffffffffu, sum8, 2);

        l0 = l0 * alpha0 + sum0;
        l8 = l8 * alpha8 + sum8;
        #pragma unroll
        for (int j = 0; j < 8; j++) {
            o[j][0] *= alpha0; o[j][1] *= alpha0;
            o[j][2] *= alpha8; o[j][3] *= alpha8;
        }

        // ---- P fragments: accumulator layout == A-fragment layout (flash trick) ----
        uint32_t ap[4][4];
        #pragma unroll
        for (int kk = 0; kk < 4; kk++) {
            int j0 = 2 * kk, j1 = 2 * kk + 1;
            ap[kk][0] = f2h2(s[j0][0], s[j0][1]);
            ap[kk][1] = f2h2(s[j0][2], s[j0][3]);
            ap[kk][2] = f2h2(s[j1][0], s[j1][1]);
            ap[kk][3] = f2h2(s[j1][2], s[j1][3]);
        }

        // ---- O += P @ V : V B-fragments are single LDS.32 from sV[dd][t] ----
        #pragma unroll
        for (int kk = 0; kk < 4; kk++) {
            int trow = 16 * kk + 2 * c4;
            #pragma unroll
            for (int j = 0; j < 8; j++) {
                int dd = 8 * j + g;
                uint32_t b0 = *reinterpret_cast<const uint32_t*>(&sV[dd * LDK + trow]);
                uint32_t b1 = *reinterpret_cast<const uint32_t*>(&sV[dd * LDK + trow + 8]);
                mma16816(o[j], ap[kk], b0, b1);
            }
        }
        __syncthreads();
    }

    // ---- Epilogue: out[b][head*64+dd][t] = o / l ----
    float il0 = 1.f / l0;
    float il8 = 1.f / l8;
    #pragma unroll
    for (int j = 0; j < 8; j++) {
        int dd = 8 * j + 2 * c4;
        ob[(size_t)(dd    ) * SEQ + qr0] = o[j][0] * il0;
        ob[(size_t)(dd + 1) * SEQ + qr0] = o[j][1] * il0;
        ob[(size_t)(dd    ) * SEQ + qr8] = o[j][2] * il8;
        ob[(size_t)(dd + 1) * SEQ + qr8] = o[j][3] * il8;
    }
}

extern "C" void kernel_launch(void* const* d_in, const int* in_sizes, int n_in,
                              void* d_out, int out_size) {
    const float* q    = (const float*)d_in[0];
    const float* k    = (const float*)d_in[1];
    const float* v    = (const float*)d_in[2];
    const float* mask = (const float*)d_in[3];
    float* out = (float*)d_out;

    dim3 grid(SEQ / BM, BATCH * NHEADS);   // (16, 64)
    dim3 block(NTHREADS);
    mha_flash_kernel<<<grid, block>>>(q, k, v, mask, out);
}

// round 5
// speedup vs baseline: 1.2241x; 1.1961x over previous
#include <cuda_runtime.h>
#include <cuda_fp16.h>
#include <cstdint>

// Problem constants
#define BATCH    8
#define NHEADS   8
#define DHEAD    64
#define SEQ      1024
#define BM       64      // q rows per CTA (4 warps x 16)
#define BN       64      // k cols per inner tile
#define NTHREADS 128
#define NKT      (SEQ / BN)   // 16
#define LDQ      72      // halves per smem row of sQ
#define LDKF     68      // fp32 words per K row  (bank: 2*68 % 32 == 8 -> 8*c4+g distinct)
#define LDVF     72      // fp32 words per V row  (LDS.64 pair-bank: 4g+c4 distinct per phase)
#define KSTAGE_W (DHEAD * LDKF)           // 4352 words
#define VSTAGE_W (DHEAD * LDVF)           // 4608 words
#define K_OFF_W(s) ((s) * KSTAGE_W)
#define V_OFF_W(s) (3 * KSTAGE_W + (s) * VSTAGE_W)
#define Q_OFF_W    (3 * KSTAGE_W + 2 * VSTAGE_W)   // sQ aliases V stage 2
#define SMEM_BYTES ((3 * KSTAGE_W + 3 * VSTAGE_W) * 4)   // 107520

__device__ __forceinline__ uint32_t packh(__half lo, __half hi) {
    return ((uint32_t)__half_as_ushort(hi) << 16) | (uint32_t)__half_as_ushort(lo);
}
__device__ __forceinline__ uint32_t f2h2(float x, float y) {
    __half2 h = __floats2half2_rn(x, y);
    return *reinterpret_cast<uint32_t*>(&h);
}
__device__ __forceinline__ void mma16816(float* d, const uint32_t* a, uint32_t b0, uint32_t b1) {
    asm volatile(
        "mma.sync.aligned.m16n8k16.row.col.f32.f16.f16.f32 "
        "{%0,%1,%2,%3}, {%4,%5,%6,%7}, {%8,%9}, {%0,%1,%2,%3};\n"
        : "+f"(d[0]), "+f"(d[1]), "+f"(d[2]), "+f"(d[3])
        : "r"(a[0]), "r"(a[1]), "r"(a[2]), "r"(a[3]), "r"(b0), "r"(b1));
}
__device__ __forceinline__ void cp16(uint32_t dst, const void* src) {
    asm volatile("cp.async.cg.shared.global [%0], [%1], 16;\n" :: "r"(dst), "l"(src));
}

__global__ __launch_bounds__(NTHREADS, 2)
void mha_flash_kernel(const float* __restrict__ q, const float* __restrict__ k,
                      const float* __restrict__ v, const float* __restrict__ mask,
                      float* __restrict__ out) {
    extern __shared__ float smem[];
    __half* sQ = reinterpret_cast<__half*>(smem + Q_OFF_W);
    const uint32_t smem_b = (uint32_t)__cvta_generic_to_shared(smem);

    const int qt    = blockIdx.x;   // 0..15
    const int bh    = blockIdx.y;   // 0..63
    const int batch = bh >> 3;
    const float* qb = q + (size_t)bh * (DHEAD * SEQ);
    const float* kb = k + (size_t)bh * (DHEAD * SEQ);
    const float* vb = v + (size_t)bh * (DHEAD * SEQ);
    const float* mb = mask + (size_t)batch * SEQ * SEQ;
    float*       ob = out + (size_t)bh * (DHEAD * SEQ);

    const int tid  = threadIdx.x;
    const int warp = tid >> 5;
    const int lane = tid & 31;
    const int g    = lane >> 2;   // 0..7
    const int c4   = lane & 3;    // 0..3

    const int t0 = qt * BM;

    // ---- Load Q tile: gmem [dd][t] fp32 -> smem fp16, fold 0.125 scale (exact) ----
    #pragma unroll
    for (int i = tid; i < DHEAD * (BM / 2); i += NTHREADS) {
        int dd = i >> 5;          // 32 float2 per row
        int t2 = i & 31;
        float2 val = *reinterpret_cast<const float2*>(qb + (size_t)dd * SEQ + t0 + 2 * t2);
        *reinterpret_cast<__half2*>(&sQ[dd * LDQ + 2 * t2]) =
            __floats2half2_rn(val.x * 0.125f, val.y * 0.125f);
    }
    __syncthreads();

    // ---- Q A-fragments, registers for whole loop ----
    const int r0 = warp * 16 + g;
    const int r8 = r0 + 8;
    uint32_t aq[4][4];
    #pragma unroll
    for (int kk = 0; kk < 4; kk++) {
        int col = 16 * kk + 2 * c4;
        aq[kk][0] = packh(sQ[(col    ) * LDQ + r0], sQ[(col + 1) * LDQ + r0]);
        aq[kk][1] = packh(sQ[(col    ) * LDQ + r8], sQ[(col + 1) * LDQ + r8]);
        aq[kk][2] = packh(sQ[(col + 8) * LDQ + r0], sQ[(col + 9) * LDQ + r0]);
        aq[kk][3] = packh(sQ[(col + 8) * LDQ + r8], sQ[(col + 9) * LDQ + r8]);
    }

    // ---- cp.async tile issue: K,V fp32 -> 3-stage smem ring (one group per kt) ----
    auto issue_tile = [&](int kt) {
        if (kt < NKT) {
            const int st = kt % 3;
            const float* kbb = kb + kt * BN;
            const float* vbb = vb + kt * BN;
            const uint32_t kdst = smem_b + K_OFF_W(st) * 4;
            const uint32_t vdst = smem_b + V_OFF_W(st) * 4;
            #pragma unroll
            for (int u = 0; u < 8; u++) {
                int i   = tid + u * NTHREADS;   // 0..1023
                int row = i >> 4;               // 0..63
                int ch  = i & 15;               // 16B chunk within 256B row
                cp16(kdst + (uint32_t)(row * LDKF + ch * 4) * 4, kbb + (size_t)row * SEQ + ch * 4);
                cp16(vdst + (uint32_t)(row * LDVF + ch * 4) * 4, vbb + (size_t)row * SEQ + ch * 4);
            }
        }
        asm volatile("cp.async.commit_group;\n");
    };

    issue_tile(0);
    issue_tile(1);
    // NOTE: stage 2 (V2 aliases sQ) is first written via issue_tile(2) AFTER the
    // kt=0 top barrier, which orders it after every thread's aq build above.

    // ---- Flash state ----
    float m0 = -1e30f, m8 = -1e30f, l0 = 0.f, l8 = 0.f;
    float o[8][4];
    #pragma unroll
    for (int j = 0; j < 8; j++) { o[j][0] = 0.f; o[j][1] = 0.f; o[j][2] = 0.f; o[j][3] = 0.f; }

    const int qr0 = t0 + r0;
    const int qr8 = t0 + r8;

    for (int kt = 0; kt < NKT; kt++) {
        // stage kt arrived (own copies) ...
        asm volatile("cp.async.wait_group 1;\n" ::: "memory");
        // ... all threads' copies visible + stage (kt+2)%3 free for reissue
        __syncthreads();

        // ---- Mask loads (L2) early: in flight under the QK MMAs ----
        const float* mrow0 = mb + (size_t)qr0 * SEQ + kt * BN;
        const float* mrow8 = mb + (size_t)qr8 * SEQ + kt * BN;
        float2 mk0[8], mk8[8];
        #pragma unroll
        for (int j = 0; j < 8; j++) {
            int cc = 8 * j + 2 * c4;
            mk0[j] = *reinterpret_cast<const float2*>(mrow0 + cc);
            mk8[j] = *reinterpret_cast<const float2*>(mrow8 + cc);
        }

        // ---- Refill the freed stage for kt+2 (async; off the critical path) ----
        issue_tile(kt + 2);

        // ---- Scores: S = (Q*0.125) @ K^T ----
        const float* kc = smem + K_OFF_W(kt % 3);
        float s[8][4];
        #pragma unroll
        for (int j = 0; j < 8; j++) { s[j][0] = 0.f; s[j][1] = 0.f; s[j][2] = 0.f; s[j][3] = 0.f; }

        #pragma unroll
        for (int kk = 0; kk < 4; kk++) {
            const float* kp = kc + (16 * kk + 2 * c4) * LDKF;
            #pragma unroll
            for (int j = 0; j < 8; j++) {
                int tk = 8 * j + g;
                uint32_t b0 = f2h2(kp[tk],            kp[LDKF + tk]);
                uint32_t b1 = f2h2(kp[8 * LDKF + tk], kp[9 * LDKF + tk]);
                mma16816(s[j], aq[kk], b0, b1);
            }
        }

        // ---- Apply mask: nonzero -> -1e30 (exp underflows to exact 0) ----
        #pragma unroll
        for (int j = 0; j < 8; j++) {
            if (mk0[j].x != 0.f) s[j][0] = -1e30f;
            if (mk0[j].y != 0.f) s[j][1] = -1e30f;
            if (mk8[j].x != 0.f) s[j][2] = -1e30f;
            if (mk8[j].y != 0.f) s[j][3] = -1e30f;
        }

        // ---- Online softmax (rows r0 and r8) ----
        float vmax0 = -1e30f, vmax8 = -1e30f;
        #pragma unroll
        for (int j = 0; j < 8; j++) {
            vmax0 = fmaxf(vmax0, fmaxf(s[j][0], s[j][1]));
            vmax8 = fmaxf(vmax8, fmaxf(s[j][2], s[j][3]));
        }
        vmax0 = fmaxf(vmax0, __shfl_xor_sync(0xffffffffu, vmax0, 1));
        vmax0 = fmaxf(vmax0, __shfl_xor_sync(0xffffffffu, vmax0, 2));
        vmax8 = fmaxf(vmax8, __shfl_xor_sync(0xffffffffu, vmax8, 1));
        vmax8 = fmaxf(vmax8, __shfl_xor_sync(0xffffffffu, vmax8, 2));

        float mn0 = fmaxf(m0, vmax0);
        float mn8 = fmaxf(m8, vmax8);
        float alpha0 = __expf(m0 - mn0);
        float alpha8 = __expf(m8 - mn8);
        m0 = mn0; m8 = mn8;

        float sum0 = 0.f, sum8 = 0.f;
        #pragma unroll
        for (int j = 0; j < 8; j++) {
            float p0 = __expf(s[j][0] - mn0);
            float p1 = __expf(s[j][1] - mn0);
            float p2 = __expf(s[j][2] - mn8);
            float p3 = __expf(s[j][3] - mn8);
            sum0 += p0 + p1;
            sum8 += p2 + p3;
            s[j][0] = p0; s[j][1] = p1; s[j][2] = p2; s[j][3] = p3;
        }
        sum0 += __shfl_xor_sync(0xffffffffu, sum0, 1);
        sum0 += __shfl_xor_sync(0xffffffffu, sum0, 2);
        sum8 += __shfl_xor_sync(0xffffffffu, sum8, 1);
        sum8 += __shfl_xor_sync(0xffffffffu, sum8, 2);

        l0 = l0 * alpha0 + sum0;
        l8 = l8 * alpha8 + sum8;
        #pragma unroll
        for (int j = 0; j < 8; j++) {
            o[j][0] *= alpha0; o[j][1] *= alpha0;
            o[j][2] *= alpha8; o[j][3] *= alpha8;
        }

        // ---- P fragments: accumulator layout == A-fragment layout ----
        uint32_t ap[4][4];
        #pragma unroll
        for (int kk = 0; kk < 4; kk++) {
            int j0 = 2 * kk, j1 = 2 * kk + 1;
            ap[kk][0] = f2h2(s[j0][0], s[j0][1]);
            ap[kk][1] = f2h2(s[j0][2], s[j0][3]);
            ap[kk][2] = f2h2(s[j1][0], s[j1][1]);
            ap[kk][3] = f2h2(s[j1][2], s[j1][3]);
        }

        // ---- O += P @ V : LDS.64 fp32 pair + pack ----
        const float* vc = smem + V_OFF_W(kt % 3);
        #pragma unroll
        for (int kk = 0; kk < 4; kk++) {
            int trow = 16 * kk + 2 * c4;
            #pragma unroll
            for (int j = 0; j < 8; j++) {
                int dd = 8 * j + g;
                float2 lv0 = *reinterpret_cast<const float2*>(vc + dd * LDVF + trow);
                float2 lv1 = *reinterpret_cast<const float2*>(vc + dd * LDVF + trow + 8);
                mma16816(o[j], ap[kk], f2h2(lv0.x, lv0.y), f2h2(lv1.x, lv1.y));
            }
        }
        // no trailing barrier: top-of-loop barrier provides reissue safety
    }

    // ---- Epilogue: out[b][head*64+dd][t] = o / l ----
    float il0 = 1.f / l0;
    float il8 = 1.f / l8;
    #pragma unroll
    for (int j = 0; j < 8; j++) {
        int dd = 8 * j + 2 * c4;
        ob[(size_t)(dd    ) * SEQ + qr0] = o[j][0] * il0;
        ob[(size_t)(dd + 1) * SEQ + qr0] = o[j][1] * il0;
        ob[(size_t)(dd    ) * SEQ + qr8] = o[j][2] * il8;
        ob[(size_t)(dd + 1) * SEQ + qr8] = o[j][3] * il8;
    }
}

extern "C" void kernel_launch(void* const* d_in, const int* in_sizes, int n_in,
                              void* d_out, int out_size) {
    const float* q    = (const float*)d_in[0];
    const float* k    = (const float*)d_in[1];
    const float* v    = (const float*)d_in[2];
    const float* mask = (const float*)d_in[3];
    float* out = (float*)d_out;

    cudaFuncSetAttribute(mha_flash_kernel,
                         cudaFuncAttributeMaxDynamicSharedMemorySize, SMEM_BYTES);

    dim3 grid(SEQ / BM, BATCH * NHEADS);   // (16, 64)
    dim3 block(NTHREADS);
    mha_flash_kernel<<<grid, block, SMEM_BYTES>>>(q, k, v, mask, out);
}

// round 6
// speedup vs baseline: 1.2749x; 1.0415x over previous
#include <cuda_runtime.h>
#include <cuda_fp16.h>
#include <cstdint>

// Problem constants
#define BATCH    8
#define NHEADS   8
#define DHEAD    64
#define SEQ      1024
#define BM       64      // q rows per CTA (4 warps x 16)
#define BN       64      // k cols per inner tile
#define NTHREADS 128
#define NKT      (SEQ / BN)   // 16
#define LDQ      72      // halves per smem row of sQ
#define LDKF     68      // fp32 words per K row  (bank: 8*c4+g distinct)
#define LDVF     72      // fp32 words per V row  (LDS.64 pair-bank: 4g+c4 distinct)
#define KSTAGE_W (DHEAD * LDKF)           // 4352 words
#define VSTAGE_W (DHEAD * LDVF)           // 4608 words
#define K_OFF_W(s) ((s) * KSTAGE_W)
#define V_OFF_W(s) (2 * KSTAGE_W + (s) * VSTAGE_W)
#define Q_OFF_W    V_OFF_W(1)             // sQ aliases V stage 1 (consumed pre-loop)
#define SMEM_BYTES ((2 * KSTAGE_W + 2 * VSTAGE_W) * 4)   // 71680 -> 3 CTAs/SM

__device__ __forceinline__ uint32_t packh(__half lo, __half hi) {
    return ((uint32_t)__half_as_ushort(hi) << 16) | (uint32_t)__half_as_ushort(lo);
}
__device__ __forceinline__ uint32_t f2h2(float x, float y) {
    __half2 h = __floats2half2_rn(x, y);
    return *reinterpret_cast<uint32_t*>(&h);
}
__device__ __forceinline__ void mma16816(float* d, const uint32_t* a, uint32_t b0, uint32_t b1) {
    asm volatile(
        "mma.sync.aligned.m16n8k16.row.col.f32.f16.f16.f32 "
        "{%0,%1,%2,%3}, {%4,%5,%6,%7}, {%8,%9}, {%0,%1,%2,%3};\n"
        : "+f"(d[0]), "+f"(d[1]), "+f"(d[2]), "+f"(d[3])
        : "r"(a[0]), "r"(a[1]), "r"(a[2]), "r"(a[3]), "r"(b0), "r"(b1));
}
__device__ __forceinline__ void cp16(uint32_t dst, const void* src) {
    asm volatile("cp.async.cg.shared.global [%0], [%1], 16;\n" :: "r"(dst), "l"(src));
}

__global__ __launch_bounds__(NTHREADS, 3)
void mha_flash_kernel(const float* __restrict__ q, const float* __restrict__ k,
                      const float* __restrict__ v, const float* __restrict__ mask,
                      float* __restrict__ out) {
    extern __shared__ float smem[];
    __half* sQ = reinterpret_cast<__half*>(smem + Q_OFF_W);
    const uint32_t smem_b = (uint32_t)__cvta_generic_to_shared(smem);

    const int qt    = blockIdx.x;   // 0..15
    const int bh    = blockIdx.y;   // 0..63
    const int batch = bh >> 3;
    const float* qb = q + (size_t)bh * (DHEAD * SEQ);
    const float* kb = k + (size_t)bh * (DHEAD * SEQ);
    const float* vb = v + (size_t)bh * (DHEAD * SEQ);
    const float* mb = mask + (size_t)batch * SEQ * SEQ;
    float*       ob = out + (size_t)bh * (DHEAD * SEQ);

    const int tid  = threadIdx.x;
    const int warp = tid >> 5;
    const int lane = tid & 31;
    const int g    = lane >> 2;   // 0..7
    const int c4   = lane & 3;    // 0..3

    const int t0 = qt * BM;

    // ---- Load Q tile: gmem [dd][t] fp32 -> smem fp16, fold 0.125 scale (exact) ----
    #pragma unroll
    for (int i = tid; i < DHEAD * (BM / 2); i += NTHREADS) {
        int dd = i >> 5;          // 32 float2 per row
        int t2 = i & 31;
        float2 val = *reinterpret_cast<const float2*>(qb + (size_t)dd * SEQ + t0 + 2 * t2);
        *reinterpret_cast<__half2*>(&sQ[dd * LDQ + 2 * t2]) =
            __floats2half2_rn(val.x * 0.125f, val.y * 0.125f);
    }
    __syncthreads();

    // ---- Q A-fragments, registers for whole loop ----
    const int r0 = warp * 16 + g;
    const int r8 = r0 + 8;
    uint32_t aq[4][4];
    #pragma unroll
    for (int kk = 0; kk < 4; kk++) {
        int col = 16 * kk + 2 * c4;
        aq[kk][0] = packh(sQ[(col    ) * LDQ + r0], sQ[(col + 1) * LDQ + r0]);
        aq[kk][1] = packh(sQ[(col    ) * LDQ + r8], sQ[(col + 1) * LDQ + r8]);
        aq[kk][2] = packh(sQ[(col + 8) * LDQ + r0], sQ[(col + 9) * LDQ + r0]);
        aq[kk][3] = packh(sQ[(col + 8) * LDQ + r8], sQ[(col + 9) * LDQ + r8]);
    }
    // All threads done reading sQ before cp.async overwrites V stage 1 (aliased).
    __syncthreads();

    // ---- cp.async tile issue: K,V fp32 -> 2-stage smem ring (one group per kt) ----
    auto issue_tile = [&](int kt) {
        if (kt < NKT) {
            const int st = kt & 1;
            const float* kbb = kb + kt * BN;
            const float* vbb = vb + kt * BN;
            const uint32_t kdst = smem_b + K_OFF_W(st) * 4;
            const uint32_t vdst = smem_b + V_OFF_W(st) * 4;
            #pragma unroll
            for (int u = 0; u < 8; u++) {
                int i   = tid + u * NTHREADS;   // 0..1023
                int row = i >> 4;               // 0..63
                int ch  = i & 15;               // 16B chunk within 256B row
                cp16(kdst + (uint32_t)(row * LDKF + ch * 4) * 4, kbb + (size_t)row * SEQ + ch * 4);
                cp16(vdst + (uint32_t)(row * LDVF + ch * 4) * 4, vbb + (size_t)row * SEQ + ch * 4);
            }
        }
        asm volatile("cp.async.commit_group;\n");
    };

    issue_tile(0);
    issue_tile(1);

    // ---- Flash state ----
    float m0 = -1e30f, m8 = -1e30f, l0 = 0.f, l8 = 0.f;
    float o[8][4];
    #pragma unroll
    for (int j = 0; j < 8; j++) { o[j][0] = 0.f; o[j][1] = 0.f; o[j][2] = 0.f; o[j][3] = 0.f; }

    const int qr0 = t0 + r0;
    const int qr8 = t0 + r8;

    for (int kt = 0; kt < NKT; kt++) {
        // tile kt arrived (own copies); barrier makes all threads' copies visible
        asm volatile("cp.async.wait_group 1;\n" ::: "memory");
        __syncthreads();

        // ---- Mask loads (L2) early: in flight under the QK MMAs ----
        const float* mrow0 = mb + (size_t)qr0 * SEQ + kt * BN;
        const float* mrow8 = mb + (size_t)qr8 * SEQ + kt * BN;
        float2 mk0[8], mk8[8];
        #pragma unroll
        for (int j = 0; j < 8; j++) {
            int cc = 8 * j + 2 * c4;
            mk0[j] = *reinterpret_cast<const float2*>(mrow0 + cc);
            mk8[j] = *reinterpret_cast<const float2*>(mrow8 + cc);
        }

        // ---- Scores: S = (Q*0.125) @ K^T ----
        const float* kc = smem + K_OFF_W(kt & 1);
        float s[8][4];
        #pragma unroll
        for (int j = 0; j < 8; j++) { s[j][0] = 0.f; s[j][1] = 0.f; s[j][2] = 0.f; s[j][3] = 0.f; }

        #pragma unroll
        for (int kk = 0; kk < 4; kk++) {
            const float* kp = kc + (16 * kk + 2 * c4) * LDKF;
            #pragma unroll
            for (int j = 0; j < 8; j++) {
                int tk = 8 * j + g;
                uint32_t b0 = f2h2(kp[tk],            kp[LDKF + tk]);
                uint32_t b1 = f2h2(kp[8 * LDKF + tk], kp[9 * LDKF + tk]);
                mma16816(s[j], aq[kk], b0, b1);
            }
        }

        // ---- Apply mask: nonzero -> -1e30 (exp underflows to exact 0) ----
        #pragma unroll
        for (int j = 0; j < 8; j++) {
            if (mk0[j].x != 0.f) s[j][0] = -1e30f;
            if (mk0[j].y != 0.f) s[j][1] = -1e30f;
            if (mk8[j].x != 0.f) s[j][2] = -1e30f;
            if (mk8[j].y != 0.f) s[j][3] = -1e30f;
        }

        // ---- Online softmax (rows r0 and r8) ----
        float vmax0 = -1e30f, vmax8 = -1e30f;
        #pragma unroll
        for (int j = 0; j < 8; j++) {
            vmax0 = fmaxf(vmax0, fmaxf(s[j][0], s[j][1]));
            vmax8 = fmaxf(vmax8, fmaxf(s[j][2], s[j][3]));
        }
        vmax0 = fmaxf(vmax0, __shfl_xor_sync(0xffffffffu, vmax0, 1));
        vmax0 = fmaxf(vmax0, __shfl_xor_sync(0xffffffffu, vmax0, 2));
        vmax8 = fmaxf(vmax8, __shfl_xor_sync(0xffffffffu, vmax8, 1));
        vmax8 = fmaxf(vmax8, __shfl_xor_sync(0xffffffffu, vmax8, 2));

        float mn0 = fmaxf(m0, vmax0);
        float mn8 = fmaxf(m8, vmax8);
        float alpha0 = __expf(m0 - mn0);
        float alpha8 = __expf(m8 - mn8);
        m0 = mn0; m8 = mn8;

        float sum0 = 0.f, sum8 = 0.f;
        #pragma unroll
        for (int j = 0; j < 8; j++) {
            float p0 = __expf(s[j][0] - mn0);
            float p1 = __expf(s[j][1] - mn0);
            float p2 = __expf(s[j][2] - mn8);
            float p3 = __expf(s[j][3] - mn8);
            sum0 += p0 + p1;
            sum8 += p2 + p3;
            s[j][0] = p0; s[j][1] = p1; s[j][2] = p2; s[j][3] = p3;
        }
        sum0 += __shfl_xor_sync(0xffffffffu, sum0, 1);
        sum0 += __shfl_xor_sync(0xffffffffu, sum0, 2);
        sum8 += __shfl_xor_sync(0xffffffffu, sum8, 1);
        sum8 += __shfl_xor_sync(0xffffffffu, sum8, 2);

        l0 = l0 * alpha0 + sum0;
        l8 = l8 * alpha8 + sum8;
        #pragma unroll
        for (int j = 0; j < 8; j++) {
            o[j][0] *= alpha0; o[j][1] *= alpha0;
            o[j][2] *= alpha8; o[j][3] *= alpha8;
        }

        // ---- P fragments: accumulator layout == A-fragment layout ----
        uint32_t ap[4][4];
        #pragma unroll
        for (int kk = 0; kk < 4; kk++) {
            int j0 = 2 * kk, j1 = 2 * kk + 1;
            ap[kk][0] = f2h2(s[j0][0], s[j0][1]);
            ap[kk][1] = f2h2(s[j0][2], s[j0][3]);
            ap[kk][2] = f2h2(s[j1][0], s[j1][1]);
            ap[kk][3] = f2h2(s[j1][2], s[j1][3]);
        }

        // ---- O += P @ V : LDS.64 fp32 pair + pack ----
        const float* vc = smem + V_OFF_W(kt & 1);
        #pragma unroll
        for (int kk = 0; kk < 4; kk++) {
            int trow = 16 * kk + 2 * c4;
            #pragma unroll
            for (int j = 0; j < 8; j++) {
                int dd = 8 * j + g;
                float2 lv0 = *reinterpret_cast<const float2*>(vc + dd * LDVF + trow);
                float2 lv1 = *reinterpret_cast<const float2*>(vc + dd * LDVF + trow + 8);
                mma16816(o[j], ap[kk], f2h2(lv0.x, lv0.y), f2h2(lv1.x, lv1.y));
            }
        }

        // all warps done reading stage kt&1 -> safe to refill it for kt+2
        __syncthreads();
        issue_tile(kt + 2);
    }

    // ---- Epilogue: out[b][head*64+dd][t] = o / l ----
    float il0 = 1.f / l0;
    float il8 = 1.f / l8;
    #pragma unroll
    for (int j = 0; j < 8; j++) {
        int dd = 8 * j + 2 * c4;
        ob[(size_t)(dd    ) * SEQ + qr0] = o[j][0] * il0;
        ob[(size_t)(dd + 1) * SEQ + qr0] = o[j][1] * il0;
        ob[(size_t)(dd    ) * SEQ + qr8] = o[j][2] * il8;
        ob[(size_t)(dd + 1) * SEQ + qr8] = o[j][3] * il8;
    }
}

extern "C" void kernel_launch(void* const* d_in, const int* in_sizes, int n_in,
                              void* d_out, int out_size) {
    const float* q    = (const float*)d_in[0];
    const float* k    = (const float*)d_in[1];
    const float* v    = (const float*)d_in[2];
    const float* mask = (const float*)d_in[3];
    float* out = (float*)d_out;

    cudaFuncSetAttribute(mha_flash_kernel,
                         cudaFuncAttributeMaxDynamicSharedMemorySize, SMEM_BYTES);

    dim3 grid(SEQ / BM, BATCH * NHEADS);   // (16, 64)
    dim3 block(NTHREADS);
    mha_flash_kernel<<<grid, block, SMEM_BYTES>>>(q, k, v, mask, out);
}